// round 15
// baseline (speedup 1.0000x reference)
#include <cuda_runtime.h>
#include <cuda_fp16.h>
#include <cstdint>

// ============================================================================
// Problem constants
// ============================================================================
#define M_DIM 8192          // 4 * 2048 tokens
#define N_DIM 4096          // out features
#define K_DIM 4096          // in features

// GEMM tiling: CTA 128x128, 4 warps (warp tile 64x64), 3 CTAs/SM, 2-stage pipe.
#define TM 128
#define TN 128
#define KSTAGE 64                       // fp16 K elems per stage = 128 bytes/row
#define NSTAGES 2
#define NK (K_DIM / KSTAGE)             // 64 k-chunks
#define A_STAGE_BYTES (TM * 128)        // 16384
#define B_STAGE_BYTES (TN * 128)        // 16384
#define STAGE_BYTES (A_STAGE_BYTES + B_STAGE_BYTES)   // 32768
#define SMEM_BYTES (NSTAGES * STAGE_BYTES)            // 65536 (x3 CTAs = 192KB/SM)

// Static device scratch (allocation-free rule: __device__ globals)
__device__ __align__(1024) __half g_Wh[(size_t)N_DIM * K_DIM];   // 32 MB
__device__ __align__(1024) __half g_Xh[(size_t)M_DIM * K_DIM];   // 64 MB

// ============================================================================
// Device helpers
// ============================================================================
__device__ __forceinline__ uint32_t smem_to_u32(const void* smem_ptr) {
    uint32_t addr;
    asm("{ .reg .u64 tmp; cvta.to.shared.u64 tmp, %1; cvt.u32.u64 %0, tmp; }"
        : "=r"(addr) : "l"(smem_ptr));
    return addr;
}

__device__ __forceinline__ void cp_async16(uint32_t dst, const void* src) {
    asm volatile("cp.async.cg.shared.global [%0], [%1], 16;\n"
                 :: "r"(dst), "l"(src) : "memory");
}
__device__ __forceinline__ void cp_commit() {
    asm volatile("cp.async.commit_group;\n" ::: "memory");
}
__device__ __forceinline__ void cp_wait0() {
    asm volatile("cp.async.wait_group 0;\n" ::: "memory");
}

__device__ __forceinline__ void ldsm_x4(uint32_t r[4], uint32_t a) {
    asm volatile("ldmatrix.sync.aligned.m8n8.x4.shared.b16 {%0,%1,%2,%3}, [%4];"
                 : "=r"(r[0]), "=r"(r[1]), "=r"(r[2]), "=r"(r[3]) : "r"(a));
}

__device__ __forceinline__ void mma16816(float c[4], const uint32_t a[4],
                                         const uint32_t b0, const uint32_t b1) {
    asm volatile(
        "mma.sync.aligned.m16n8k16.row.col.f32.f16.f16.f32 "
        "{%0,%1,%2,%3}, {%4,%5,%6,%7}, {%8,%9}, {%0,%1,%2,%3};"
        : "+f"(c[0]), "+f"(c[1]), "+f"(c[2]), "+f"(c[3])
        : "r"(a[0]), "r"(a[1]), "r"(a[2]), "r"(a[3]), "r"(b0), "r"(b1));
}

// ============================================================================
// Pre-pass kernels
// ============================================================================
// packed: int32 holding two 4-bit codes (low, high). codes index 2i, 2i+1.
// group = code_idx / 128 = i / 64. w = code * scale[g] + offset[g].
__global__ void dequant_kernel(const int* __restrict__ packed,
                               const float* __restrict__ scales,
                               const float* __restrict__ offsets) {
    int t = blockIdx.x * blockDim.x + threadIdx.x;     // 16B chunk of packed
    const int NT = (N_DIM * K_DIM / 2) / 4;            // 2,097,152
    if (t >= NT) return;
    int4 p = ((const int4*)packed)[t];
    int base = t * 4;                 // packed element index (4 per chunk, same group)
    int g = base >> 6;                // 64 packed elems per group of 128 codes
    float s = __ldg(scales + g), o = __ldg(offsets + g);
    int pv[4] = {p.x, p.y, p.z, p.w};
    __half2 h[4];
#pragma unroll
    for (int j = 0; j < 4; j++)
        h[j] = __floats2half2_rn((float)(pv[j] & 15) * s + o,
                                 (float)((pv[j] >> 4) & 15) * s + o);
    ((int4*)g_Wh)[t] = *reinterpret_cast<int4*>(h);
}

__global__ void xconv_kernel(const float* __restrict__ x) {
    size_t t = (size_t)blockIdx.x * blockDim.x + threadIdx.x;   // float4 chunk
    const size_t NT = (size_t)M_DIM * K_DIM / 4;
    if (t >= NT) return;
    float4 v = ((const float4*)x)[t];
    __half2 a = __floats2half2_rn(v.x, v.y);
    __half2 b = __floats2half2_rn(v.z, v.w);
    uint2 u;
    u.x = *reinterpret_cast<uint32_t*>(&a);
    u.y = *reinterpret_cast<uint32_t*>(&b);
    ((uint2*)g_Xh)[t] = u;
}

// ============================================================================
// GEMM: out[8192,4096] = Xh @ Wh^T + bias
// mma.sync m16n8k16 fp16->fp32, cp.async 2-stage pipeline, XOR-swizzled smem.
// CTA 128x128, 4 warps 2(m) x 2(n), warp tile 64x64, 3 CTAs/SM: while one CTA
// stalls on cp_wait/barrier, two other CTAs keep the SMSP tensor pipes fed.
// ============================================================================
__global__ void __launch_bounds__(128, 3)
gemm_kernel(const float* __restrict__ bias, float* __restrict__ out) {
    extern __shared__ char smem[];
    const uint32_t sbase = smem_to_u32(smem);

    const int tid = threadIdx.x;
    const int wid = tid >> 5, lane = tid & 31;
    const int wm = wid >> 1, wn = wid & 1;           // warp grid 2(m) x 2(n)
    const int m0 = blockIdx.y * TM;
    const int n0 = blockIdx.x * TN;

    // ---- cp.async per-thread assignment (16B chunks; 8 A + 8 B per thread)
    // chunk = tid + 128*j  =>  row = tid/8 + 16j, col16 = tid%8 (constant)
    const int row0 = tid >> 3;
    const int c16 = tid & 7;
    const int swc = (c16 ^ (row0 & 7)) * 16;         // swizzled column bytes (const)
    const __half* aSrc0 = g_Xh + (size_t)(m0 + row0) * K_DIM + c16 * 8;
    const __half* bSrc0 = g_Wh + (size_t)(n0 + row0) * K_DIM + c16 * 8;
    const uint32_t aDst0 = sbase + row0 * 128 + swc;
    const uint32_t bDst0 = sbase + A_STAGE_BYTES + row0 * 128 + swc;

    // ---- ldmatrix per-thread addresses
    // XOR swizzle: col ^ ((row & 7) * 16); row&7 == lane&7 for both A and B.
    const uint32_t xr = (lane & 7) * 16;
    // A x4: lanes 0-15 = m-rows (klo), lanes 16-31 = same rows (khi)
    const uint32_t aRowBase = (wm * 64 + (lane & 15)) * 128;
    const uint32_t aHi = (lane >> 4) * 16;
    // B x4 (two n8 tiles per load): n_local = p*2 + (lane>>4), k_half = (lane>>3)&1
    const uint32_t bRowBase = (wn * 64 + (lane >> 4) * 8 + (lane & 7)) * 128;
    const uint32_t bHi = ((lane >> 3) & 1) * 16;

    float acc[4][8][4];
#pragma unroll
    for (int mt = 0; mt < 4; mt++)
#pragma unroll
        for (int nt = 0; nt < 8; nt++)
#pragma unroll
            for (int r = 0; r < 4; r++) acc[mt][nt][r] = 0.0f;

    // ---- prologue: issue stage 0
    {
#pragma unroll
        for (int j = 0; j < 8; j++)
            cp_async16(aDst0 + j * 2048, aSrc0 + (size_t)j * 16 * K_DIM);
#pragma unroll
        for (int j = 0; j < 8; j++)
            cp_async16(bDst0 + j * 2048, bSrc0 + (size_t)j * 16 * K_DIM);
        cp_commit();
    }

    // ---- main loop (2-deep ring: compute slot i&1, load slot (i+1)&1)
#pragma unroll 1
    for (int i = 0; i < NK; i++) {
        cp_wait0();
        __syncthreads();   // all readers of slot (i+1)&1 (from iter i-1) are done

        const uint32_t slotA = sbase + (i & 1) * STAGE_BYTES;
        const uint32_t slotB = slotA + A_STAGE_BYTES;

        // issue stage i+1 into the other slot
        if (i + 1 < NK) {
            const uint32_t soff = ((i + 1) & 1) * STAGE_BYTES;
            const size_t koff = (size_t)(i + 1) * KSTAGE;
#pragma unroll
            for (int j = 0; j < 8; j++)
                cp_async16(aDst0 + soff + j * 2048, aSrc0 + koff + (size_t)j * 16 * K_DIM);
#pragma unroll
            for (int j = 0; j < 8; j++)
                cp_async16(bDst0 + soff + j * 2048, bSrc0 + koff + (size_t)j * 16 * K_DIM);
        }
        cp_commit();   // empty group when no loads keeps wait_group bookkeeping exact

        // compute on stage i
#pragma unroll
        for (int kk = 0; kk < 4; kk++) {
            const uint32_t aCol = (kk * 32 + aHi) ^ xr;
            const uint32_t bCol = (kk * 32 + bHi) ^ xr;
            uint32_t af[4][4];
#pragma unroll
            for (int mt = 0; mt < 4; mt++)
                ldsm_x4(af[mt], slotA + aRowBase + mt * 2048 + aCol);
#pragma unroll
            for (int p = 0; p < 4; p++) {
                uint32_t bf[4];
                ldsm_x4(bf, slotB + bRowBase + p * 2048 + bCol);
#pragma unroll
                for (int mt = 0; mt < 4; mt++) {
                    mma16816(acc[mt][2 * p], af[mt], bf[0], bf[1]);
                    mma16816(acc[mt][2 * p + 1], af[mt], bf[2], bf[3]);
                }
            }
        }
    }

    // ---- epilogue: add bias, write fp32
    const int rBase = m0 + wm * 64 + (lane >> 2);
    const int cBase = n0 + wn * 64 + (lane & 3) * 2;
#pragma unroll
    for (int nt = 0; nt < 8; nt++) {
        const int c = cBase + nt * 8;
        const float b0 = __ldg(bias + c);
        const float b1 = __ldg(bias + c + 1);
#pragma unroll
        for (int mt = 0; mt < 4; mt++) {
            const int r = rBase + mt * 16;
            float2 v0 = make_float2(acc[mt][nt][0] + b0, acc[mt][nt][1] + b1);
            float2 v1 = make_float2(acc[mt][nt][2] + b0, acc[mt][nt][3] + b1);
            *reinterpret_cast<float2*>(out + (size_t)r * N_DIM + c) = v0;
            *reinterpret_cast<float2*>(out + (size_t)(r + 8) * N_DIM + c) = v1;
        }
    }
}

// ============================================================================
// Host launch
// ============================================================================
extern "C" void kernel_launch(void* const* d_in, const int* in_sizes, int n_in,
                              void* d_out, int out_size) {
    const float* x       = (const float*)d_in[0];
    const int*   packed  = (const int*)d_in[1];
    const float* scales  = (const float*)d_in[2];
    const float* offsets = (const float*)d_in[3];
    const float* bias    = (const float*)d_in[4];
    float* out = (float*)d_out;

    // Pre-pass: dequant W and convert x to fp16
    {
        const int nt_w = (N_DIM * K_DIM / 2) / 4;
        dequant_kernel<<<(nt_w + 255) / 256, 256>>>(packed, scales, offsets);
        const int nt_x = (int)((size_t)M_DIM * K_DIM / 4);
        xconv_kernel<<<(nt_x + 255) / 256, 256>>>(x);
    }

    static bool attr_set = false;
    if (!attr_set) {
        cudaFuncSetAttribute(gemm_kernel,
                             cudaFuncAttributeMaxDynamicSharedMemorySize, SMEM_BYTES);
        attr_set = true;
    }
    dim3 grid(N_DIM / TN, M_DIM / TM);   // (32, 64)
    gemm_kernel<<<grid, 128, SMEM_BYTES>>>(bias, out);
}

// round 16
// speedup vs baseline: 1.1056x; 1.1056x over previous
#include <cuda_runtime.h>
#include <cuda_fp16.h>
#include <cstdint>

// ============================================================================
// Problem constants
// ============================================================================
#define M_DIM 8192          // 4 * 2048 tokens
#define N_DIM 4096          // out features
#define K_DIM 4096          // in features

// GEMM tiling: CTA 128x128, 4 warps (warp tile 64x64), 2 CTAs/SM, 3-stage pipe.
#define TM 128
#define TN 128
#define KSTAGE 64                       // fp16 K elems per stage = 128 bytes/row
#define NSTAGES 3
#define NK (K_DIM / KSTAGE)             // 64 k-chunks
#define A_STAGE_BYTES (TM * 128)        // 16384
#define B_STAGE_BYTES (TN * 128)        // 16384
#define STAGE_BYTES (A_STAGE_BYTES + B_STAGE_BYTES)   // 32768
#define SMEM_BYTES (NSTAGES * STAGE_BYTES)            // 98304 (x2 CTAs = 192KB/SM)

// Static device scratch (allocation-free rule: __device__ globals)
__device__ __align__(1024) __half g_Wh[(size_t)N_DIM * K_DIM];   // 32 MB
__device__ __align__(1024) __half g_Xh[(size_t)M_DIM * K_DIM];   // 64 MB

// ============================================================================
// Device helpers
// ============================================================================
__device__ __forceinline__ uint32_t smem_to_u32(const void* smem_ptr) {
    uint32_t addr;
    asm("{ .reg .u64 tmp; cvta.to.shared.u64 tmp, %1; cvt.u32.u64 %0, tmp; }"
        : "=r"(addr) : "l"(smem_ptr));
    return addr;
}

__device__ __forceinline__ void cp_async16(uint32_t dst, const void* src) {
    asm volatile("cp.async.cg.shared.global [%0], [%1], 16;\n"
                 :: "r"(dst), "l"(src) : "memory");
}
__device__ __forceinline__ void cp_commit() {
    asm volatile("cp.async.commit_group;\n" ::: "memory");
}
__device__ __forceinline__ void cp_wait1() {
    asm volatile("cp.async.wait_group 1;\n" ::: "memory");
}

__device__ __forceinline__ void ldsm_x4(uint32_t r[4], uint32_t a) {
    asm volatile("ldmatrix.sync.aligned.m8n8.x4.shared.b16 {%0,%1,%2,%3}, [%4];"
                 : "=r"(r[0]), "=r"(r[1]), "=r"(r[2]), "=r"(r[3]) : "r"(a));
}

__device__ __forceinline__ void mma16816(float c[4], const uint32_t a[4],
                                         const uint32_t b0, const uint32_t b1) {
    asm volatile(
        "mma.sync.aligned.m16n8k16.row.col.f32.f16.f16.f32 "
        "{%0,%1,%2,%3}, {%4,%5,%6,%7}, {%8,%9}, {%0,%1,%2,%3};"
        : "+f"(c[0]), "+f"(c[1]), "+f"(c[2]), "+f"(c[3])
        : "r"(a[0]), "r"(a[1]), "r"(a[2]), "r"(a[3]), "r"(b0), "r"(b1));
}

// ============================================================================
// Pre-pass kernels
// ============================================================================
// packed: int32 holding two 4-bit codes (low, high). codes index 2i, 2i+1.
// group = code_idx / 128 = i / 64. w = code * scale[g] + offset[g].
__global__ void dequant_kernel(const int* __restrict__ packed,
                               const float* __restrict__ scales,
                               const float* __restrict__ offsets) {
    int t = blockIdx.x * blockDim.x + threadIdx.x;     // 16B chunk of packed
    const int NT = (N_DIM * K_DIM / 2) / 4;            // 2,097,152
    if (t >= NT) return;
    int4 p = ((const int4*)packed)[t];
    int base = t * 4;                 // packed element index (4 per chunk, same group)
    int g = base >> 6;                // 64 packed elems per group of 128 codes
    float s = __ldg(scales + g), o = __ldg(offsets + g);
    int pv[4] = {p.x, p.y, p.z, p.w};
    __half2 h[4];
#pragma unroll
    for (int j = 0; j < 4; j++)
        h[j] = __floats2half2_rn((float)(pv[j] & 15) * s + o,
                                 (float)((pv[j] >> 4) & 15) * s + o);
    ((int4*)g_Wh)[t] = *reinterpret_cast<int4*>(h);
}

__global__ void xconv_kernel(const float* __restrict__ x) {
    size_t t = (size_t)blockIdx.x * blockDim.x + threadIdx.x;   // float4 chunk
    const size_t NT = (size_t)M_DIM * K_DIM / 4;
    if (t >= NT) return;
    float4 v = ((const float4*)x)[t];
    __half2 a = __floats2half2_rn(v.x, v.y);
    __half2 b = __floats2half2_rn(v.z, v.w);
    uint2 u;
    u.x = *reinterpret_cast<uint32_t*>(&a);
    u.y = *reinterpret_cast<uint32_t*>(&b);
    ((uint2*)g_Xh)[t] = u;
}

// ============================================================================
// GEMM: out[8192,4096] = Xh @ Wh^T + bias
// mma.sync m16n8k16 fp16->fp32, cp.async 3-stage pipeline, XOR-swizzled smem.
// CTA 128x128, 4 warps 2(m) x 2(n), warp tile 64x64, 2 CTAs/SM (cross-CTA
// overlap of barriers/epilogue), plus register double-buffered fragments:
// head fragments load first so the next-stage cp.async burst hides their
// latency, then kk+1 LDSMs hide under kk's MMA stream.
// ============================================================================
__global__ void __launch_bounds__(128, 2)
gemm_kernel(const float* __restrict__ bias, float* __restrict__ out) {
    extern __shared__ char smem[];
    const uint32_t sbase = smem_to_u32(smem);

    const int tid = threadIdx.x;
    const int wid = tid >> 5, lane = tid & 31;
    const int wm = wid >> 1, wn = wid & 1;           // warp grid 2(m) x 2(n)
    const int m0 = blockIdx.y * TM;
    const int n0 = blockIdx.x * TN;

    // ---- cp.async per-thread assignment (16B chunks; 8 A + 8 B per thread)
    // chunk = tid + 128*j  =>  row = tid/8 + 16j, col16 = tid%8 (constant)
    const int row0 = tid >> 3;
    const int c16 = tid & 7;
    const int swc = (c16 ^ (row0 & 7)) * 16;         // swizzled column bytes (const)
    const __half* aSrc0 = g_Xh + (size_t)(m0 + row0) * K_DIM + c16 * 8;
    const __half* bSrc0 = g_Wh + (size_t)(n0 + row0) * K_DIM + c16 * 8;
    const uint32_t aDst0 = sbase + row0 * 128 + swc;
    const uint32_t bDst0 = sbase + A_STAGE_BYTES + row0 * 128 + swc;

    // ---- ldmatrix per-thread addresses
    // XOR swizzle: col ^ ((row & 7) * 16); row&7 == lane&7 for both A and B.
    const uint32_t xr = (lane & 7) * 16;
    // A x4: lanes 0-15 = m-rows (klo), lanes 16-31 = same rows (khi)
    const uint32_t aRowBase = (wm * 64 + (lane & 15)) * 128;
    const uint32_t aHi = (lane >> 4) * 16;
    // B x4 (two n8 tiles per load): n_local = p*2 + (lane>>4), k_half = (lane>>3)&1
    const uint32_t bRowBase = (wn * 64 + (lane >> 4) * 8 + (lane & 7)) * 128;
    const uint32_t bHi = ((lane >> 3) & 1) * 16;

    float acc[4][8][4];
#pragma unroll
    for (int mt = 0; mt < 4; mt++)
#pragma unroll
        for (int nt = 0; nt < 8; nt++)
#pragma unroll
            for (int r = 0; r < 4; r++) acc[mt][nt][r] = 0.0f;

    // ---- prologue: issue stages 0..1
#pragma unroll
    for (int s = 0; s < NSTAGES - 1; s++) {
        const uint32_t soff = s * STAGE_BYTES;
        const size_t koff = (size_t)s * KSTAGE;
#pragma unroll
        for (int j = 0; j < 8; j++)
            cp_async16(aDst0 + soff + j * 2048, aSrc0 + koff + (size_t)j * 16 * K_DIM);
#pragma unroll
        for (int j = 0; j < 8; j++)
            cp_async16(bDst0 + soff + j * 2048, bSrc0 + koff + (size_t)j * 16 * K_DIM);
        cp_commit();
    }

    // Fragment double buffers
    uint32_t af[2][4][4], bf[2][4][4];

#define LOAD_FRAGS(buf, slotA, slotB, kk) do {                                  \
        const uint32_t _aCol = ((kk) * 32 + aHi) ^ xr;                          \
        const uint32_t _bCol = ((kk) * 32 + bHi) ^ xr;                          \
        _Pragma("unroll")                                                       \
        for (int _mt = 0; _mt < 4; _mt++)                                       \
            ldsm_x4(af[buf][_mt], (slotA) + aRowBase + _mt * 2048 + _aCol);     \
        _Pragma("unroll")                                                       \
        for (int _p = 0; _p < 4; _p++)                                          \
            ldsm_x4(bf[buf][_p], (slotB) + bRowBase + _p * 2048 + _bCol);       \
    } while (0)

    // ---- main loop (3-deep ring: compute slot i%3, issue slot (i+2)%3)
#pragma unroll 1
    for (int i = 0; i < NK; i++) {
        cp_wait1();        // this warp's stage-i group complete
        __syncthreads();   // all warps' stage-i data visible; slot (i+2)%3 free

        const uint32_t slotA = sbase + (i % NSTAGES) * STAGE_BYTES;
        const uint32_t slotB = slotA + A_STAGE_BYTES;

        // head fragments first: their LDS latency hides under the cp burst below
        LOAD_FRAGS(0, slotA, slotB, 0);

        // issue stage i+2 into the freed slot
        if (i + 2 < NK) {
            const uint32_t soff = ((i + 2) % NSTAGES) * STAGE_BYTES;
            const size_t koff = (size_t)(i + 2) * KSTAGE;
#pragma unroll
            for (int j = 0; j < 8; j++)
                cp_async16(aDst0 + soff + j * 2048, aSrc0 + koff + (size_t)j * 16 * K_DIM);
#pragma unroll
            for (int j = 0; j < 8; j++)
                cp_async16(bDst0 + soff + j * 2048, bSrc0 + koff + (size_t)j * 16 * K_DIM);
        }
        cp_commit();   // empty group when no loads keeps wait_group bookkeeping exact

        // compute: prefetch kk+1 fragments, then MMAs of kk
#pragma unroll
        for (int kk = 0; kk < 4; kk++) {
            const int cur = kk & 1;
            if (kk < 3) LOAD_FRAGS(cur ^ 1, slotA, slotB, kk + 1);
#pragma unroll
            for (int p = 0; p < 4; p++)
#pragma unroll
                for (int mt = 0; mt < 4; mt++) {
                    mma16816(acc[mt][2 * p], af[cur][mt], bf[cur][p][0], bf[cur][p][1]);
                    mma16816(acc[mt][2 * p + 1], af[cur][mt], bf[cur][p][2], bf[cur][p][3]);
                }
        }
    }
#undef LOAD_FRAGS

    // ---- epilogue: add bias, write fp32
    const int rBase = m0 + wm * 64 + (lane >> 2);
    const int cBase = n0 + wn * 64 + (lane & 3) * 2;
#pragma unroll
    for (int nt = 0; nt < 8; nt++) {
        const int c = cBase + nt * 8;
        const float b0 = __ldg(bias + c);
        const float b1 = __ldg(bias + c + 1);
#pragma unroll
        for (int mt = 0; mt < 4; mt++) {
            const int r = rBase + mt * 16;
            float2 v0 = make_float2(acc[mt][nt][0] + b0, acc[mt][nt][1] + b1);
            float2 v1 = make_float2(acc[mt][nt][2] + b0, acc[mt][nt][3] + b1);
            *reinterpret_cast<float2*>(out + (size_t)r * N_DIM + c) = v0;
            *reinterpret_cast<float2*>(out + (size_t)(r + 8) * N_DIM + c) = v1;
        }
    }
}

// ============================================================================
// Host launch
// ============================================================================
extern "C" void kernel_launch(void* const* d_in, const int* in_sizes, int n_in,
                              void* d_out, int out_size) {
    const float* x       = (const float*)d_in[0];
    const int*   packed  = (const int*)d_in[1];
    const float* scales  = (const float*)d_in[2];
    const float* offsets = (const float*)d_in[3];
    const float* bias    = (const float*)d_in[4];
    float* out = (float*)d_out;

    // Pre-pass: dequant W and convert x to fp16
    {
        const int nt_w = (N_DIM * K_DIM / 2) / 4;
        dequant_kernel<<<(nt_w + 255) / 256, 256>>>(packed, scales, offsets);
        const int nt_x = (int)((size_t)M_DIM * K_DIM / 4);
        xconv_kernel<<<(nt_x + 255) / 256, 256>>>(x);
    }

    static bool attr_set = false;
    if (!attr_set) {
        cudaFuncSetAttribute(gemm_kernel,
                             cudaFuncAttributeMaxDynamicSharedMemorySize, SMEM_BYTES);
        attr_set = true;
    }
    dim3 grid(N_DIM / TN, M_DIM / TM);   // (32, 64)
    gemm_kernel<<<grid, 128, SMEM_BYTES>>>(bias, out);
}